// round 2
// baseline (speedup 1.0000x reference)
#include <cuda_runtime.h>
#include <math.h>

#define SEQ   2048
#define BATCH 2
#define NH    16
#define DKV   64
#define DM    1024
#define MTOT  (BATCH*SEQ)

// Scratch (allocation-free: static device globals)
__device__ __align__(16) float g_q[BATCH*NH*SEQ*DKV];
__device__ __align__(16) float g_k[BATCH*NH*SEQ*DKV];
__device__ __align__(16) float g_v[BATCH*NH*SEQ*DKV];
__device__ __align__(16) float g_ctx[MTOT*DM];

// ---------------------------------------------------------------------------
// Classic 128x128x8 SGEMM, 256 threads, 8x8 microtile per thread.
// mode 0: C row-major [M,N].  mode 1: scatter to head-major [B,H,S,Dk].
// ---------------------------------------------------------------------------
__global__ __launch_bounds__(256) void sgemm_kernel(
    const float* __restrict__ A, const float* __restrict__ B,
    float* __restrict__ C, int M, int N, int K, int mode)
{
    __shared__ float As[8][128];
    __shared__ float Bs[8][128];
    const int tid  = threadIdx.x;
    const int row0 = blockIdx.y * 128;
    const int col0 = blockIdx.x * 128;
    const int aRow = tid >> 1, aCol = (tid & 1) * 4;
    const int bRow = tid >> 5, bCol = (tid & 31) * 4;
    const int ty = tid >> 4, tx = tid & 15;

    float acc[8][8];
    #pragma unroll
    for (int i = 0; i < 8; i++)
        #pragma unroll
        for (int j = 0; j < 8; j++) acc[i][j] = 0.f;

    const float* Aptr = A + (size_t)(row0 + aRow) * K + aCol;
    const float* Bptr = B + (size_t)bRow * N + col0 + bCol;

    for (int k0 = 0; k0 < K; k0 += 8) {
        float4 av = *(const float4*)(Aptr + k0);
        float4 bv = *(const float4*)(Bptr + (size_t)k0 * N);
        As[aCol+0][aRow] = av.x;
        As[aCol+1][aRow] = av.y;
        As[aCol+2][aRow] = av.z;
        As[aCol+3][aRow] = av.w;
        *(float4*)&Bs[bRow][bCol] = bv;
        __syncthreads();
        #pragma unroll
        for (int kk = 0; kk < 8; kk++) {
            float ra[8], rb[8];
            #pragma unroll
            for (int i = 0; i < 8; i++) ra[i] = As[kk][ty*8+i];
            #pragma unroll
            for (int j = 0; j < 8; j++) rb[j] = Bs[kk][tx*8+j];
            #pragma unroll
            for (int i = 0; i < 8; i++)
                #pragma unroll
                for (int j = 0; j < 8; j++)
                    acc[i][j] = fmaf(ra[i], rb[j], acc[i][j]);
        }
        __syncthreads();
    }

    if (mode == 0) {
        #pragma unroll
        for (int i = 0; i < 8; i++) {
            int r = row0 + ty*8 + i;
            float* cp = C + (size_t)r * N + col0 + tx*8;
            *(float4*)cp       = make_float4(acc[i][0], acc[i][1], acc[i][2], acc[i][3]);
            *(float4*)(cp + 4) = make_float4(acc[i][4], acc[i][5], acc[i][6], acc[i][7]);
        }
    } else {
        // head-major scatter: row r = b*SEQ+s, col c = h*DKV+d
        int c0 = col0 + tx*8;
        int hh = c0 >> 6, dd = c0 & 63;
        #pragma unroll
        for (int i = 0; i < 8; i++) {
            int r  = row0 + ty*8 + i;
            int bb = r >> 11, ss = r & (SEQ-1);
            float* cp = C + (((size_t)(bb*NH + hh) * SEQ) + ss) * DKV + dd;
            *(float4*)cp       = make_float4(acc[i][0], acc[i][1], acc[i][2], acc[i][3]);
            *(float4*)(cp + 4) = make_float4(acc[i][4], acc[i][5], acc[i][6], acc[i][7]);
        }
    }
}

// ---------------------------------------------------------------------------
// Flash attention with T5 relative-position bias.
// Grid: (SEQ/64, NH, BATCH), 256 threads (8 warps x 8 q-rows each).
// ---------------------------------------------------------------------------
#define ATTN_SMEM_FLOATS (4096 + 2112 + 2048 + 2048 + 2112 + 32)
#define ATTN_SMEM_BYTES  (ATTN_SMEM_FLOATS * 4)

__global__ __launch_bounds__(256) void attn_kernel(const float* __restrict__ rel_emb)
{
    extern __shared__ float sm[];
    float* Qs    = sm;            // [64][64]
    float* Kts   = sm + 4096;     // [64][33]  (K transposed, padded)
    float* Vs    = sm + 6208;     // [32][64]
    float* Ps    = sm + 8256;     // [8 warps][8 rows][32]
    float* biasS = sm + 10304;    // [2111] bias values for this (q0, h)
    float* embh  = sm + 12416;    // [32] rel_emb column for head h

    const int tid = threadIdx.x;
    const int b  = blockIdx.z, h = blockIdx.y;
    const int q0 = blockIdx.x * 64;

    const float* Qp = g_q + (((size_t)b*NH + h)*SEQ + q0) * DKV;
    const float* Kp = g_k + ((size_t)b*NH + h)*SEQ*DKV;
    const float* Vp = g_v + ((size_t)b*NH + h)*SEQ*DKV;

    #pragma unroll
    for (int i = 0; i < 4; i++) {
        int idx = (tid + i*256) * 4;
        *(float4*)&Qs[idx] = *(const float4*)&Qp[idx];
    }
    if (tid < 32) embh[tid] = rel_emb[tid*NH + h];
    __syncthreads();

    // Inline T5 bidirectional bucket -> bias slice for rel = k - q in
    // [-(q0+63), 2047-q0], index j = rel + q0 + 63.
    for (int j = tid; j < 2111; j += 256) {
        int rel = j - (q0 + 63);     // mem - ctx
        int n = -rel;                // ctx - mem
        int ret = 0;
        if (n < 0) { ret = 16; n = -n; }
        int bkt;
        if (n < 8) bkt = n;
        else {
            float t = logf((float)n * 0.125f);
            t = t / 2.7725887222397812f;   // f32(log(16)); == 4*f32(log 2) bit-exact
            t = t * 8.0f;
            int v = 8 + (int)t;
            bkt = v < 15 ? v : 15;
        }
        biasS[j] = embh[ret + bkt];
    }

    const int w = tid >> 5, lane = tid & 31;
    const int r0 = w * 8;
    float m[8], l[8], a0[8], a1[8];
    #pragma unroll
    for (int r = 0; r < 8; r++) { m[r] = -3.0e38f; l[r] = 0.f; a0[r] = 0.f; a1[r] = 0.f; }

    const int kRow = tid >> 3;
    const int cc   = (tid & 7) * 8;

    for (int kv0 = 0; kv0 < SEQ; kv0 += 32) {
        __syncthreads();   // previous tile compute done (and bias ready on iter 0)
        {
            const float* kp = Kp + (size_t)(kv0 + kRow)*DKV + cc;
            float4 ka = *(const float4*)kp;
            float4 kb = *(const float4*)(kp + 4);
            Kts[(cc+0)*33 + kRow] = ka.x;
            Kts[(cc+1)*33 + kRow] = ka.y;
            Kts[(cc+2)*33 + kRow] = ka.z;
            Kts[(cc+3)*33 + kRow] = ka.w;
            Kts[(cc+4)*33 + kRow] = kb.x;
            Kts[(cc+5)*33 + kRow] = kb.y;
            Kts[(cc+6)*33 + kRow] = kb.z;
            Kts[(cc+7)*33 + kRow] = kb.w;
            const float* vp = Vp + (size_t)(kv0 + kRow)*DKV + cc;
            *(float4*)&Vs[kRow*DKV + cc]     = *(const float4*)vp;
            *(float4*)&Vs[kRow*DKV + cc + 4] = *(const float4*)(vp + 4);
        }
        __syncthreads();

        // scores: each lane owns kv column (kv0+lane), 8 q-rows
        float sc[8];
        #pragma unroll
        for (int r = 0; r < 8; r++) sc[r] = 0.f;
        #pragma unroll 4
        for (int d4 = 0; d4 < 64; d4 += 4) {
            float k0v = Kts[(d4+0)*33 + lane];
            float k1v = Kts[(d4+1)*33 + lane];
            float k2v = Kts[(d4+2)*33 + lane];
            float k3v = Kts[(d4+3)*33 + lane];
            #pragma unroll
            for (int r = 0; r < 8; r++) {
                float4 qv = *(const float4*)&Qs[(r0+r)*64 + d4];
                sc[r] = fmaf(qv.x, k0v, sc[r]);
                sc[r] = fmaf(qv.y, k1v, sc[r]);
                sc[r] = fmaf(qv.z, k2v, sc[r]);
                sc[r] = fmaf(qv.w, k3v, sc[r]);
            }
        }

        // bias + online softmax update
        #pragma unroll
        for (int r = 0; r < 8; r++) {
            float s = sc[r] + biasS[kv0 + lane - r0 - r + 63];
            float tm = s;
            #pragma unroll
            for (int o = 16; o; o >>= 1)
                tm = fmaxf(tm, __shfl_xor_sync(0xffffffffu, tm, o));
            float mnew = fmaxf(m[r], tm);
            float p    = exp2f((s    - mnew) * 1.44269504f);
            float corr = exp2f((m[r] - mnew) * 1.44269504f);
            float ts = p;
            #pragma unroll
            for (int o = 16; o; o >>= 1)
                ts += __shfl_xor_sync(0xffffffffu, ts, o);
            l[r] = l[r]*corr + ts;
            m[r] = mnew;
            a0[r] *= corr; a1[r] *= corr;
            Ps[(r0 + r)*32 + lane] = p;
        }
        __syncwarp();

        // accumulate P @ V (lane owns output dims lane and lane+32)
        #pragma unroll 2
        for (int k4 = 0; k4 < 32; k4 += 4) {
            float v00 = Vs[(k4+0)*64 + lane], v01 = Vs[(k4+0)*64 + 32 + lane];
            float v10 = Vs[(k4+1)*64 + lane], v11 = Vs[(k4+1)*64 + 32 + lane];
            float v20 = Vs[(k4+2)*64 + lane], v21 = Vs[(k4+2)*64 + 32 + lane];
            float v30 = Vs[(k4+3)*64 + lane], v31 = Vs[(k4+3)*64 + 32 + lane];
            #pragma unroll
            for (int r = 0; r < 8; r++) {
                float4 pv = *(const float4*)&Ps[(r0+r)*32 + k4];
                a0[r] = fmaf(pv.x, v00, a0[r]); a1[r] = fmaf(pv.x, v01, a1[r]);
                a0[r] = fmaf(pv.y, v10, a0[r]); a1[r] = fmaf(pv.y, v11, a1[r]);
                a0[r] = fmaf(pv.z, v20, a0[r]); a1[r] = fmaf(pv.z, v21, a1[r]);
                a0[r] = fmaf(pv.w, v30, a0[r]); a1[r] = fmaf(pv.w, v31, a1[r]);
            }
        }
        __syncwarp();
    }

    // epilogue: ctx[b, q, h*64 + d]
    #pragma unroll
    for (int r = 0; r < 8; r++) {
        float inv = 1.0f / l[r];
        int q = q0 + r0 + r;
        float* op = g_ctx + ((size_t)(b*SEQ + q))*DM + h*DKV;
        op[lane]      = a0[r] * inv;
        op[lane + 32] = a1[r] * inv;
    }
}

// ---------------------------------------------------------------------------
extern "C" void kernel_launch(void* const* d_in, const int* in_sizes, int n_in,
                              void* d_out, int out_size)
{
    const float* x   = (const float*)d_in[0];
    const float* wq  = (const float*)d_in[1];
    const float* wk  = (const float*)d_in[2];
    const float* wv  = (const float*)d_in[3];
    const float* wo  = (const float*)d_in[4];
    const float* rel = (const float*)d_in[5];
    float* out = (float*)d_out;

    float *dq, *dk, *dv, *dctx;
    cudaGetSymbolAddress((void**)&dq,   g_q);
    cudaGetSymbolAddress((void**)&dk,   g_k);
    cudaGetSymbolAddress((void**)&dv,   g_v);
    cudaGetSymbolAddress((void**)&dctx, g_ctx);

    cudaFuncSetAttribute(attn_kernel,
                         cudaFuncAttributeMaxDynamicSharedMemorySize,
                         ATTN_SMEM_BYTES);

    dim3 gg(DM/128, MTOT/128), bb(256);
    sgemm_kernel<<<gg, bb>>>(x, wq, dq, MTOT, DM, DM, 1);
    sgemm_kernel<<<gg, bb>>>(x, wk, dk, MTOT, DM, DM, 1);
    sgemm_kernel<<<gg, bb>>>(x, wv, dv, MTOT, DM, DM, 1);
    attn_kernel<<<dim3(SEQ/64, NH, BATCH), 256, ATTN_SMEM_BYTES>>>(rel);
    sgemm_kernel<<<gg, bb>>>(dctx, wo, out, MTOT, DM, DM, 0);
}